// round 10
// baseline (speedup 1.0000x reference)
#include <cuda_runtime.h>
#include <math.h>

#define NPAD 129
#define NT   512     // kA/kB block size
#define NTC  1024    // kC block size (64-reg budget)
#define PI_F 3.14159265358979f

// ---------------- device scratch (static: no allocation allowed) -------------
__device__ float2 g_ihat [64  * 16384];    // FFT2(image), digit-rev layout
__device__ float2 g_u1hat[1024 * 16384];   // FFT2(|u1|),  digit-rev layout
__device__ float  g_psi  [16  * 16384];    // Morlet bank, digit-rev layout
__device__ float  g_s0   [64];
__device__ float  g_s1part[1024];
__device__ float  g_s2part[6144];

// digit-reversal for radix [8,4,4] DIF: freq f -> storage position
__device__ __forceinline__ int dperm(int f) {
    return ((f & 7) << 4) | (((f >> 3) & 3) << 2) | (f >> 5);
}

// ---------------- filter bank, stored pre-permuted ---------------------------
__global__ void init_psi_kernel() {
    int idx = blockIdx.x * blockDim.x + threadIdx.x;
    if (idx >= 16 * 16384) return;
    int fc = idx & 127;
    int fr = (idx >> 7) & 127;
    int l  = (idx >> 14) & 3;
    int j  = idx >> 16;
    const float w = 2.f * PI_F / 128.f;
    float fx = (float)((fr < 64) ? fr : fr - 128) * w;
    float fy = (float)((fc < 64) ? fc : fc - 128) * w;
    float k0 = (3.f * PI_F / 4.f) / (float)(1 << j);
    float sg = 0.8f * (float)(1 << j);
    float th = PI_F * (float)l / 4.f;
    float k0x = k0 * cosf(th), k0y = k0 * sinf(th);
    float hs = 0.5f * sg * sg;
    float beta = expf(-hs * k0 * k0);
    float gs = expf(-hs * ((fx - k0x) * (fx - k0x) + (fy - k0y) * (fy - k0y)));
    float g0 = expf(-hs * (fx * fx + fy * fy));
    g_psi[((j * 4 + l) << 14) + (dperm(fr) << 7) + dperm(fc)] = gs - beta * g0;
}

// ---------------- register butterflies (interleaved complex) -----------------
template <bool INV>
__device__ __forceinline__ void bfly4(float2* x) {
    float t0r = x[0].x + x[2].x, t0i = x[0].y + x[2].y;
    float t1r = x[0].x - x[2].x, t1i = x[0].y - x[2].y;
    float t2r = x[1].x + x[3].x, t2i = x[1].y + x[3].y;
    float t3r = x[1].x - x[3].x, t3i = x[1].y - x[3].y;
    x[0].x = t0r + t2r; x[0].y = t0i + t2i;
    x[2].x = t0r - t2r; x[2].y = t0i - t2i;
    if (!INV) {
        x[1].x = t1r + t3i; x[1].y = t1i - t3r;
        x[3].x = t1r - t3i; x[3].y = t1i + t3r;
    } else {
        x[1].x = t1r - t3i; x[1].y = t1i + t3r;
        x[3].x = t1r + t3i; x[3].y = t1i - t3r;
    }
}

template <bool INV>
__device__ __forceinline__ void bfly8(float2* x) {
    const float C = 0.70710678118654752f;
    float t0r = x[0].x + x[4].x, t0i = x[0].y + x[4].y;
    float t1r = x[0].x - x[4].x, t1i = x[0].y - x[4].y;
    float t2r = x[2].x + x[6].x, t2i = x[2].y + x[6].y;
    float t3r = x[2].x - x[6].x, t3i = x[2].y - x[6].y;
    float e0r = t0r + t2r, e0i = t0i + t2i;
    float e2r = t0r - t2r, e2i = t0i - t2i;
    float e1r, e1i, e3r, e3i;
    if (!INV) { e1r = t1r + t3i; e1i = t1i - t3r; e3r = t1r - t3i; e3i = t1i + t3r; }
    else      { e1r = t1r - t3i; e1i = t1i + t3r; e3r = t1r + t3i; e3i = t1i - t3r; }
    float u0r = x[1].x + x[5].x, u0i = x[1].y + x[5].y;
    float u1r = x[1].x - x[5].x, u1i = x[1].y - x[5].y;
    float u2r = x[3].x + x[7].x, u2i = x[3].y + x[7].y;
    float u3r = x[3].x - x[7].x, u3i = x[3].y - x[7].y;
    float o0r = u0r + u2r, o0i = u0i + u2i;
    float o2r = u0r - u2r, o2i = u0i - u2i;
    float o1r, o1i, o3r, o3i;
    if (!INV) { o1r = u1r + u3i; o1i = u1i - u3r; o3r = u1r - u3i; o3i = u1i + u3r; }
    else      { o1r = u1r - u3i; o1i = u1i + u3r; o3r = u1r + u3i; o3i = u1i - u3r; }
    float w1r, w1i, w2r, w2i, w3r, w3i;
    if (!INV) {
        w1r = C * (o1r + o1i); w1i = C * (o1i - o1r);
        w2r = o2i;             w2i = -o2r;
        w3r = C * (o3i - o3r); w3i = -C * (o3r + o3i);
    } else {
        w1r = C * (o1r - o1i); w1i = C * (o1i + o1r);
        w2r = -o2i;            w2i = o2r;
        w3r = -C * (o3r + o3i); w3i = C * (o3r - o3i);
    }
    x[0].x = e0r + o0r; x[0].y = e0i + o0i;
    x[1].x = e1r + w1r; x[1].y = e1i + w1i;
    x[2].x = e2r + w2r; x[2].y = e2i + w2i;
    x[3].x = e3r + w3r; x[3].y = e3i + w3i;
    x[4].x = e0r - o0r; x[4].y = e0i - o0i;
    x[5].x = e1r - w1r; x[5].y = e1i - w1i;
    x[6].x = e2r - w2r; x[6].y = e2i - w2i;
    x[7].x = e3r - w3r; x[7].y = e3i - w3i;
}

// ---- combined [r4-mid (stride4) + r4-last (stride1)] on 16 register points --
template <bool INV>
__device__ __forceinline__ void comb_regs(float2* x, const float* twr, const float* twi) {
    if (!INV) {
#pragma unroll
        for (int j = 0; j < 4; j++) {
            float2 y[4];
#pragma unroll
            for (int k = 0; k < 4; k++) y[k] = x[j + 4 * k];
            bfly4<false>(y);
#pragma unroll
            for (int k = 1; k < 4; k++) {
                int ti = 8 * j * k;
                float wr = twr[ti], wi = twi[ti];
                float a = y[k].x, b = y[k].y;
                y[k].x = a * wr - b * wi; y[k].y = a * wi + b * wr;
            }
#pragma unroll
            for (int k = 0; k < 4; k++) x[j + 4 * k] = y[k];
        }
#pragma unroll
        for (int a = 0; a < 4; a++) bfly4<false>(&x[4 * a]);
    } else {
#pragma unroll
        for (int a = 0; a < 4; a++) bfly4<true>(&x[4 * a]);
#pragma unroll
        for (int j = 0; j < 4; j++) {
            float2 y[4];
#pragma unroll
            for (int k = 0; k < 4; k++) y[k] = x[j + 4 * k];
#pragma unroll
            for (int k = 1; k < 4; k++) {
                int ti = 8 * j * k;
                float wr = twr[ti], wi = -twi[ti];
                float a = y[k].x, b = y[k].y;
                y[k].x = a * wr - b * wi; y[k].y = a * wi + b * wr;
            }
            bfly4<true>(y);
#pragma unroll
            for (int k = 0; k < 4; k++) x[j + 4 * k] = y[k];
        }
    }
}

// ---------------- smem passes (templated on block size BS) -------------------
template <int BS, bool INV, int DIM>
__device__ __forceinline__ void comb_stage(float2* sc, const float* twr, const float* twi) {
    for (int idx = threadIdx.x; idx < 1024; idx += BS) {
        int q = idx & 127, g = idx >> 7;
        int base = (DIM == 0) ? q * NPAD + (g << 4) : (g << 4) * NPAD + q;
        int step = (DIM == 0) ? 1 : NPAD;
        float2 x[16];
#pragma unroll
        for (int m = 0; m < 16; m++) x[m] = sc[base + m * step];
        comb_regs<INV>(x, twr, twi);
#pragma unroll
        for (int m = 0; m < 16; m++) sc[base + m * step] = x[m];
    }
    __syncthreads();
}

template <int BS, bool INV, int DIM>
__device__ __forceinline__ void r8_stage(float2* sc, const float* twr, const float* twi) {
    for (int idx = threadIdx.x; idx < 2048; idx += BS) {
        int q = idx & 127, j = idx >> 7;
        int base = (DIM == 0) ? q * NPAD + j : j * NPAD + q;
        int step = (DIM == 0) ? 16 : 16 * NPAD;
        float2 x[8];
#pragma unroll
        for (int k = 0; k < 8; k++) x[k] = sc[base + k * step];
        if (INV) {
#pragma unroll
            for (int k = 1; k < 8; k++) {
                int t = j * k;
                float wr = twr[t], wi = -twi[t];
                float a = x[k].x, b = x[k].y;
                x[k].x = a * wr - b * wi; x[k].y = a * wi + b * wr;
            }
        }
        bfly8<INV>(x);
        if (!INV) {
#pragma unroll
            for (int k = 1; k < 8; k++) {
                int t = j * k;
                float wr = twr[t], wi = twi[t];
                float a = x[k].x, b = x[k].y;
                x[k].x = a * wr - b * wi; x[k].y = a * wi + b * wr;
            }
        }
#pragma unroll
        for (int k = 0; k < 8; k++) sc[base + k * step] = x[k];
    }
    __syncthreads();
}

template <int BS>
__device__ __forceinline__ void pass_load_inv0(float2* sc, const float2* __restrict__ src,
                                               const float* __restrict__ psi,
                                               const float* twr, const float* twi) {
    const float scale = 1.f / 16384.f;
    for (int idx = threadIdx.x; idx < 1024; idx += BS) {
        int rr = idx & 127, g = idx >> 7;
        int gbase = rr * 128 + (g << 4);
        const float4* s4 = reinterpret_cast<const float4*>(src + gbase);
        const float4* p4 = reinterpret_cast<const float4*>(psi + gbase);
        float2 x[16];
#pragma unroll
        for (int m8 = 0; m8 < 4; m8++) {
            float4 p = p4[m8];
            float4 v0 = s4[m8 * 2], v1 = s4[m8 * 2 + 1];
            float pa = p.x * scale, pb = p.y * scale, pc = p.z * scale, pd = p.w * scale;
            x[m8 * 4 + 0] = make_float2(v0.x * pa, v0.y * pa);
            x[m8 * 4 + 1] = make_float2(v0.z * pb, v0.w * pb);
            x[m8 * 4 + 2] = make_float2(v1.x * pc, v1.y * pc);
            x[m8 * 4 + 3] = make_float2(v1.z * pd, v1.w * pd);
        }
        comb_regs<true>(x, twr, twi);
        int base = rr * NPAD + (g << 4);
#pragma unroll
        for (int m = 0; m < 16; m++) sc[base + m] = x[m];
    }
    __syncthreads();
}

template <int BS, bool WRITE>
__device__ __forceinline__ float pass_inv1_r8_mag(float2* sc, const float* twr, const float* twi) {
    float local = 0.f;
    for (int idx = threadIdx.x; idx < 2048; idx += BS) {
        int q = idx & 127, j = idx >> 7;
        int base = j * NPAD + q;
        int step = 16 * NPAD;
        float2 x[8];
#pragma unroll
        for (int k = 0; k < 8; k++) x[k] = sc[base + k * step];
#pragma unroll
        for (int k = 1; k < 8; k++) {
            int t = j * k;
            float wr = twr[t], wi = -twi[t];
            float a = x[k].x, b = x[k].y;
            x[k].x = a * wr - b * wi; x[k].y = a * wi + b * wr;
        }
        bfly8<true>(x);
#pragma unroll
        for (int k = 0; k < 8; k++) {
            float mag = sqrtf(x[k].x * x[k].x + x[k].y * x[k].y);
            local += mag;
            if (WRITE) sc[base + k * step] = make_float2(mag, 0.f);
        }
    }
    __syncthreads();
    return local;
}

template <int BS>
__device__ __forceinline__ void pass_fwd1_store(float2* sc, float2* __restrict__ dst,
                                                const float* twr, const float* twi) {
    for (int idx = threadIdx.x; idx < 1024; idx += BS) {
        int q = idx & 127, g = idx >> 7;
        int base = (g << 4) * NPAD + q;
        float2 x[16];
#pragma unroll
        for (int m = 0; m < 16; m++) x[m] = sc[base + m * NPAD];
        comb_regs<false>(x, twr, twi);
#pragma unroll
        for (int m = 0; m < 16; m++) dst[((g << 4) + m) * 128 + q] = x[m];
    }
}

#define INIT_TWIDDLES()                                                        \
    do {                                                                       \
        if (threadIdx.x < 128) {                                               \
            float sv, cv;                                                      \
            __sincosf(-2.f * PI_F * (float)threadIdx.x / 128.f, &sv, &cv);     \
            s_twr[threadIdx.x] = cv;                                           \
            s_twi[threadIdx.x] = sv;                                           \
        }                                                                      \
    } while (0)

// warp-shuffle block reduction (deterministic); result valid in tid 0
template <int BS>
__device__ __forceinline__ float block_sum(float v, float* red) {
#pragma unroll
    for (int o = 16; o; o >>= 1) v += __shfl_xor_sync(0xffffffffu, v, o);
    if ((threadIdx.x & 31) == 0) red[threadIdx.x >> 5] = v;
    __syncthreads();
    float s = 0.f;
    if (threadIdx.x < 32) {
        s = (threadIdx.x < BS / 32) ? red[threadIdx.x] : 0.f;
#pragma unroll
        for (int o = 16; o; o >>= 1) s += __shfl_xor_sync(0xffffffffu, s, o);
    }
    return s;
}

// ---------------- stage A: i_hat = FFT2(image), s0 ---------------------------
__global__ __launch_bounds__(NT, 1) void kA(const float* __restrict__ img) {
    extern __shared__ float2 sc[];
    __shared__ float s_twr[128], s_twi[128];
    __shared__ float red[32];
    int b = blockIdx.x;
    int tid = threadIdx.x;
    INIT_TWIDDLES();

    float local = 0.f;
    for (int idx = tid; idx < 16384; idx += NT) {
        float v = img[b * 16384 + idx];
        int r = idx >> 7, c = idx & 127;
        sc[r * NPAD + c] = make_float2(v, 0.f);
        local += v;
    }
    float s = block_sum<NT>(local, red);
    if (tid == 0) g_s0[b] = s * (1.f / 16384.f);
    __syncthreads();

    r8_stage<NT, false, 0>(sc, s_twr, s_twi);
    comb_stage<NT, false, 0>(sc, s_twr, s_twi);
    r8_stage<NT, false, 1>(sc, s_twr, s_twi);
    comb_stage<NT, false, 1>(sc, s_twr, s_twi);

    for (int idx = tid; idx < 16384; idx += NT) {
        int r = idx >> 7, c = idx & 127;
        g_ihat[b * 16384 + idx] = sc[r * NPAD + c];
    }
}

// ---------------- stage B: u1 = |ifft2(i_hat*psi)|, s1 partial, u1_hat -------
__global__ __launch_bounds__(NT, 1) void kB() {
    extern __shared__ float2 sc[];
    __shared__ float s_twr[128], s_twi[128];
    __shared__ float red[32];
    int bi = blockIdx.x;              // b*16 + j1*4 + l1
    int b  = bi >> 4;
    int j1 = (bi >> 2) & 3;
    int tid = threadIdx.x;
    INIT_TWIDDLES();
    __syncthreads();

    const float2* src = g_ihat + (size_t)b * 16384;
    const float*  psi1 = g_psi + (((size_t)(bi & 15)) << 14);

    pass_load_inv0<NT>(sc, src, psi1, s_twr, s_twi);
    r8_stage<NT, true, 0>(sc, s_twr, s_twi);
    comb_stage<NT, true, 1>(sc, s_twr, s_twi);
    float local = pass_inv1_r8_mag<NT, true>(sc, s_twr, s_twi);
    float s = block_sum<NT>(local, red);
    if (tid == 0) g_s1part[bi] = s;
    __syncthreads();

    if (j1 < 3) {                     // j1 == 3 never consumed by second order
        r8_stage<NT, false, 0>(sc, s_twr, s_twi);
        comb_stage<NT, false, 0>(sc, s_twr, s_twi);
        r8_stage<NT, false, 1>(sc, s_twr, s_twi);
        pass_fwd1_store<NT>(sc, g_u1hat + (size_t)bi * 16384, s_twr, s_twi);
    }
}

// ---------------- stage C: 4-pass inverse + |.|, 1024 threads ----------------
__global__ __launch_bounds__(NTC, 1) void kC() {
    extern __shared__ float2 sc[];
    __shared__ float s_twr[128], s_twi[128];
    __shared__ float red[32];
    int bi = blockIdx.x;              // b*96 + pair*16 + l1*4 + l2
    int b    = bi / 96;
    int r96  = bi % 96;
    int pair = r96 >> 4;
    int l1   = (r96 >> 2) & 3;
    int l2   = r96 & 3;
    const int J1[6] = {0, 0, 0, 1, 1, 2};
    const int J2[6] = {1, 2, 3, 2, 3, 3};
    int j1 = J1[pair], j2 = J2[pair];
    int tid = threadIdx.x;
    INIT_TWIDDLES();
    __syncthreads();

    const float2* src = g_u1hat + (((size_t)b * 16 + j1 * 4 + l1) << 14);
    const float*  psi = g_psi + (((size_t)j2 * 4 + l2) << 14);

    pass_load_inv0<NTC>(sc, src, psi, s_twr, s_twi);          // inv dim0: comb16
    r8_stage<NTC, true, 0>(sc, s_twr, s_twi);                 // inv dim0: r8
    comb_stage<NTC, true, 1>(sc, s_twr, s_twi);               // inv dim1: comb16
    float local = pass_inv1_r8_mag<NTC, false>(sc, s_twr, s_twi); // inv dim1: r8+|.|
    float s = block_sum<NTC>(local, red);
    if (tid == 0) g_s2part[bi] = s;
}

// ---------------- stage D: deterministic reduce + MLP ------------------------
__global__ void kD(const float* __restrict__ fc1w, const float* __restrict__ fc1b,
                   const float* __restrict__ fc2w, const float* __restrict__ fc2b,
                   float* __restrict__ out) {
    int b = threadIdx.x;
    if (b >= 64) return;
    float s[11];
    s[0] = g_s0[b];
    for (int j = 0; j < 4; j++) {
        float acc = 0.f;
        for (int l = 0; l < 4; l++) acc += g_s1part[b * 16 + j * 4 + l];
        s[1 + j] = acc * (1.f / (4.f * 16384.f));
    }
    for (int p = 0; p < 6; p++) {
        float acc = 0.f;
        for (int kk = 0; kk < 16; kk++) acc += g_s2part[b * 96 + p * 16 + kk];
        s[5 + p] = acc * (1.f / (16.f * 16384.f));
    }
    float h[4];
    for (int i = 0; i < 4; i++) {
        float a = fc1b[i];
        for (int t = 0; t < 11; t++) a += fc1w[i * 11 + t] * s[t];
        h[i] = fmaxf(a, 0.f);
    }
    for (int kk = 0; kk < 10; kk++) {
        float a = fc2b[kk];
        for (int i = 0; i < 4; i++) a += fc2w[kk * 4 + i] * h[i];
        out[b * 10 + kk] = 1.f / (1.f + expf(-a));
    }
}

// ---------------- launch -----------------------------------------------------
extern "C" void kernel_launch(void* const* d_in, const int* in_sizes, int n_in,
                              void* d_out, int out_size) {
    const float* img  = (const float*)d_in[0];
    const float* fc1w = (const float*)d_in[1];
    const float* fc1b = (const float*)d_in[2];
    const float* fc2w = (const float*)d_in[3];
    const float* fc2b = (const float*)d_in[4];
    float* out = (float*)d_out;

    const size_t smem = 128 * NPAD * sizeof(float2);   // 132096 B
    cudaFuncSetAttribute(kA, cudaFuncAttributeMaxDynamicSharedMemorySize, (int)smem);
    cudaFuncSetAttribute(kB, cudaFuncAttributeMaxDynamicSharedMemorySize, (int)smem);
    cudaFuncSetAttribute(kC, cudaFuncAttributeMaxDynamicSharedMemorySize, (int)smem);

    init_psi_kernel<<<256, 1024>>>();
    kA<<<64, NT, smem>>>(img);
    kB<<<1024, NT, smem>>>();
    kC<<<6144, NTC, smem>>>();
    kD<<<1, 64>>>(fc1w, fc1b, fc2w, fc2b, out);
}

// round 11
// speedup vs baseline: 1.3352x; 1.3352x over previous
#include <cuda_runtime.h>
#include <cuda_fp16.h>
#include <math.h>

#define NPAD 129     // fp32 smem layout (kA/kB), float2 units
#define SPAD 129     // fp16 smem layout (kC), half2 units
#define NT   512     // kA/kB block size
#define NTC  512     // kC block size, 2 CTAs/SM
#define PI_F 3.14159265358979f

// ---------------- device scratch (static: no allocation allowed) -------------
__device__ float2  g_ihat [64  * 16384];   // FFT2(image), digit-rev layout (fp32)
__device__ __half2 g_u1hat[1024 * 16384];  // FFT2(|u1|),  digit-rev layout (fp16)
__device__ float   g_psi  [16  * 16384];   // Morlet bank, digit-rev (fp32, kB)
__device__ __half  g_psih [16  * 16384];   // Morlet bank, digit-rev (fp16, kC)
__device__ float   g_s0   [64];
__device__ float   g_s1part[1024];
__device__ float   g_s2part[6144];

// digit-reversal for radix [8,4,4] DIF: freq f -> storage position
__device__ __forceinline__ int dperm(int f) {
    return ((f & 7) << 4) | (((f >> 3) & 3) << 2) | (f >> 5);
}

// ---------------- filter bank, stored pre-permuted ---------------------------
__global__ void init_psi_kernel() {
    int idx = blockIdx.x * blockDim.x + threadIdx.x;
    if (idx >= 16 * 16384) return;
    int fc = idx & 127;
    int fr = (idx >> 7) & 127;
    int l  = (idx >> 14) & 3;
    int j  = idx >> 16;
    const float w = 2.f * PI_F / 128.f;
    float fx = (float)((fr < 64) ? fr : fr - 128) * w;
    float fy = (float)((fc < 64) ? fc : fc - 128) * w;
    float k0 = (3.f * PI_F / 4.f) / (float)(1 << j);
    float sg = 0.8f * (float)(1 << j);
    float th = PI_F * (float)l / 4.f;
    float k0x = k0 * cosf(th), k0y = k0 * sinf(th);
    float hs = 0.5f * sg * sg;
    float beta = expf(-hs * k0 * k0);
    float gs = expf(-hs * ((fx - k0x) * (fx - k0x) + (fy - k0y) * (fy - k0y)));
    float g0 = expf(-hs * (fx * fx + fy * fy));
    float v = gs - beta * g0;
    int pos = ((j * 4 + l) << 14) + (dperm(fr) << 7) + dperm(fc);
    g_psi[pos]  = v;
    g_psih[pos] = __float2half(v);
}

// ---------------- register butterflies (interleaved complex) -----------------
template <bool INV>
__device__ __forceinline__ void bfly4(float2* x) {
    float t0r = x[0].x + x[2].x, t0i = x[0].y + x[2].y;
    float t1r = x[0].x - x[2].x, t1i = x[0].y - x[2].y;
    float t2r = x[1].x + x[3].x, t2i = x[1].y + x[3].y;
    float t3r = x[1].x - x[3].x, t3i = x[1].y - x[3].y;
    x[0].x = t0r + t2r; x[0].y = t0i + t2i;
    x[2].x = t0r - t2r; x[2].y = t0i - t2i;
    if (!INV) {
        x[1].x = t1r + t3i; x[1].y = t1i - t3r;
        x[3].x = t1r - t3i; x[3].y = t1i + t3r;
    } else {
        x[1].x = t1r - t3i; x[1].y = t1i + t3r;
        x[3].x = t1r + t3i; x[3].y = t1i - t3r;
    }
}

template <bool INV>
__device__ __forceinline__ void bfly8(float2* x) {
    const float C = 0.70710678118654752f;
    float t0r = x[0].x + x[4].x, t0i = x[0].y + x[4].y;
    float t1r = x[0].x - x[4].x, t1i = x[0].y - x[4].y;
    float t2r = x[2].x + x[6].x, t2i = x[2].y + x[6].y;
    float t3r = x[2].x - x[6].x, t3i = x[2].y - x[6].y;
    float e0r = t0r + t2r, e0i = t0i + t2i;
    float e2r = t0r - t2r, e2i = t0i - t2i;
    float e1r, e1i, e3r, e3i;
    if (!INV) { e1r = t1r + t3i; e1i = t1i - t3r; e3r = t1r - t3i; e3i = t1i + t3r; }
    else      { e1r = t1r - t3i; e1i = t1i + t3r; e3r = t1r + t3i; e3i = t1i - t3r; }
    float u0r = x[1].x + x[5].x, u0i = x[1].y + x[5].y;
    float u1r = x[1].x - x[5].x, u1i = x[1].y - x[5].y;
    float u2r = x[3].x + x[7].x, u2i = x[3].y + x[7].y;
    float u3r = x[3].x - x[7].x, u3i = x[3].y - x[7].y;
    float o0r = u0r + u2r, o0i = u0i + u2i;
    float o2r = u0r - u2r, o2i = u0i - u2i;
    float o1r, o1i, o3r, o3i;
    if (!INV) { o1r = u1r + u3i; o1i = u1i - u3r; o3r = u1r - u3i; o3i = u1i + u3r; }
    else      { o1r = u1r - u3i; o1i = u1i + u3r; o3r = u1r + u3i; o3i = u1i - u3r; }
    float w1r, w1i, w2r, w2i, w3r, w3i;
    if (!INV) {
        w1r = C * (o1r + o1i); w1i = C * (o1i - o1r);
        w2r = o2i;             w2i = -o2r;
        w3r = C * (o3i - o3r); w3i = -C * (o3r + o3i);
    } else {
        w1r = C * (o1r - o1i); w1i = C * (o1i + o1r);
        w2r = -o2i;            w2i = o2r;
        w3r = -C * (o3r + o3i); w3i = C * (o3r - o3i);
    }
    x[0].x = e0r + o0r; x[0].y = e0i + o0i;
    x[1].x = e1r + w1r; x[1].y = e1i + w1i;
    x[2].x = e2r + w2r; x[2].y = e2i + w2i;
    x[3].x = e3r + w3r; x[3].y = e3i + w3i;
    x[4].x = e0r - o0r; x[4].y = e0i - o0i;
    x[5].x = e1r - w1r; x[5].y = e1i - w1i;
    x[6].x = e2r - w2r; x[6].y = e2i - w2i;
    x[7].x = e3r - w3r; x[7].y = e3i - w3i;
}

// ---- combined [r4-mid (stride4) + r4-last (stride1)] on 16 register points --
template <bool INV>
__device__ __forceinline__ void comb_regs(float2* x, const float* twr, const float* twi) {
    if (!INV) {
#pragma unroll
        for (int j = 0; j < 4; j++) {
            float2 y[4];
#pragma unroll
            for (int k = 0; k < 4; k++) y[k] = x[j + 4 * k];
            bfly4<false>(y);
#pragma unroll
            for (int k = 1; k < 4; k++) {
                int ti = 8 * j * k;
                float wr = twr[ti], wi = twi[ti];
                float a = y[k].x, b = y[k].y;
                y[k].x = a * wr - b * wi; y[k].y = a * wi + b * wr;
            }
#pragma unroll
            for (int k = 0; k < 4; k++) x[j + 4 * k] = y[k];
        }
#pragma unroll
        for (int a = 0; a < 4; a++) bfly4<false>(&x[4 * a]);
    } else {
#pragma unroll
        for (int a = 0; a < 4; a++) bfly4<true>(&x[4 * a]);
#pragma unroll
        for (int j = 0; j < 4; j++) {
            float2 y[4];
#pragma unroll
            for (int k = 0; k < 4; k++) y[k] = x[j + 4 * k];
#pragma unroll
            for (int k = 1; k < 4; k++) {
                int ti = 8 * j * k;
                float wr = twr[ti], wi = -twi[ti];
                float a = y[k].x, b = y[k].y;
                y[k].x = a * wr - b * wi; y[k].y = a * wi + b * wr;
            }
            bfly4<true>(y);
#pragma unroll
            for (int k = 0; k < 4; k++) x[j + 4 * k] = y[k];
        }
    }
}

// ---------------- fp32 smem passes (kA / kB) ---------------------------------
template <int BS, bool INV, int DIM>
__device__ __forceinline__ void comb_stage(float2* sc, const float* twr, const float* twi) {
    for (int idx = threadIdx.x; idx < 1024; idx += BS) {
        int q = idx & 127, g = idx >> 7;
        int base = (DIM == 0) ? q * NPAD + (g << 4) : (g << 4) * NPAD + q;
        int step = (DIM == 0) ? 1 : NPAD;
        float2 x[16];
#pragma unroll
        for (int m = 0; m < 16; m++) x[m] = sc[base + m * step];
        comb_regs<INV>(x, twr, twi);
#pragma unroll
        for (int m = 0; m < 16; m++) sc[base + m * step] = x[m];
    }
    __syncthreads();
}

template <int BS, bool INV, int DIM>
__device__ __forceinline__ void r8_stage(float2* sc, const float* twr, const float* twi) {
    for (int idx = threadIdx.x; idx < 2048; idx += BS) {
        int q = idx & 127, j = idx >> 7;
        int base = (DIM == 0) ? q * NPAD + j : j * NPAD + q;
        int step = (DIM == 0) ? 16 : 16 * NPAD;
        float2 x[8];
#pragma unroll
        for (int k = 0; k < 8; k++) x[k] = sc[base + k * step];
        if (INV) {
#pragma unroll
            for (int k = 1; k < 8; k++) {
                int t = j * k;
                float wr = twr[t], wi = -twi[t];
                float a = x[k].x, b = x[k].y;
                x[k].x = a * wr - b * wi; x[k].y = a * wi + b * wr;
            }
        }
        bfly8<INV>(x);
        if (!INV) {
#pragma unroll
            for (int k = 1; k < 8; k++) {
                int t = j * k;
                float wr = twr[t], wi = twi[t];
                float a = x[k].x, b = x[k].y;
                x[k].x = a * wr - b * wi; x[k].y = a * wi + b * wr;
            }
        }
#pragma unroll
        for (int k = 0; k < 8; k++) sc[base + k * step] = x[k];
    }
    __syncthreads();
}

template <int BS>
__device__ __forceinline__ void pass_load_inv0(float2* sc, const float2* __restrict__ src,
                                               const float* __restrict__ psi,
                                               const float* twr, const float* twi) {
    const float scale = 1.f / 16384.f;
    for (int idx = threadIdx.x; idx < 1024; idx += BS) {
        int rr = idx & 127, g = idx >> 7;
        int gbase = rr * 128 + (g << 4);
        const float4* s4 = reinterpret_cast<const float4*>(src + gbase);
        const float4* p4 = reinterpret_cast<const float4*>(psi + gbase);
        float2 x[16];
#pragma unroll
        for (int m8 = 0; m8 < 4; m8++) {
            float4 p = p4[m8];
            float4 v0 = s4[m8 * 2], v1 = s4[m8 * 2 + 1];
            float pa = p.x * scale, pb = p.y * scale, pc = p.z * scale, pd = p.w * scale;
            x[m8 * 4 + 0] = make_float2(v0.x * pa, v0.y * pa);
            x[m8 * 4 + 1] = make_float2(v0.z * pb, v0.w * pb);
            x[m8 * 4 + 2] = make_float2(v1.x * pc, v1.y * pc);
            x[m8 * 4 + 3] = make_float2(v1.z * pd, v1.w * pd);
        }
        comb_regs<true>(x, twr, twi);
        int base = rr * NPAD + (g << 4);
#pragma unroll
        for (int m = 0; m < 16; m++) sc[base + m] = x[m];
    }
    __syncthreads();
}

template <int BS, bool WRITE>
__device__ __forceinline__ float pass_inv1_r8_mag(float2* sc, const float* twr, const float* twi) {
    float local = 0.f;
    for (int idx = threadIdx.x; idx < 2048; idx += BS) {
        int q = idx & 127, j = idx >> 7;
        int base = j * NPAD + q;
        int step = 16 * NPAD;
        float2 x[8];
#pragma unroll
        for (int k = 0; k < 8; k++) x[k] = sc[base + k * step];
#pragma unroll
        for (int k = 1; k < 8; k++) {
            int t = j * k;
            float wr = twr[t], wi = -twi[t];
            float a = x[k].x, b = x[k].y;
            x[k].x = a * wr - b * wi; x[k].y = a * wi + b * wr;
        }
        bfly8<true>(x);
#pragma unroll
        for (int k = 0; k < 8; k++) {
            float mag = sqrtf(x[k].x * x[k].x + x[k].y * x[k].y);
            local += mag;
            if (WRITE) sc[base + k * step] = make_float2(mag, 0.f);
        }
    }
    __syncthreads();
    return local;
}

// final forward combined dim1 -> gmem store as half2 (coalesced per leg)
template <int BS>
__device__ __forceinline__ void pass_fwd1_store(float2* sc, __half2* __restrict__ dst,
                                                const float* twr, const float* twi) {
    for (int idx = threadIdx.x; idx < 1024; idx += BS) {
        int q = idx & 127, g = idx >> 7;
        int base = (g << 4) * NPAD + q;
        float2 x[16];
#pragma unroll
        for (int m = 0; m < 16; m++) x[m] = sc[base + m * NPAD];
        comb_regs<false>(x, twr, twi);
#pragma unroll
        for (int m = 0; m < 16; m++)
            dst[((g << 4) + m) * 128 + q] = __float22half2_rn(x[m]);
    }
}

#define INIT_TWIDDLES()                                                        \
    do {                                                                       \
        if (threadIdx.x < 128) {                                               \
            float sv, cv;                                                      \
            __sincosf(-2.f * PI_F * (float)threadIdx.x / 128.f, &sv, &cv);     \
            s_twr[threadIdx.x] = cv;                                           \
            s_twi[threadIdx.x] = sv;                                           \
        }                                                                      \
    } while (0)

// warp-shuffle block reduction (deterministic); result valid in tid 0
template <int BS>
__device__ __forceinline__ float block_sum(float v, float* red) {
#pragma unroll
    for (int o = 16; o; o >>= 1) v += __shfl_xor_sync(0xffffffffu, v, o);
    if ((threadIdx.x & 31) == 0) red[threadIdx.x >> 5] = v;
    __syncthreads();
    float s = 0.f;
    if (threadIdx.x < 32) {
        s = (threadIdx.x < BS / 32) ? red[threadIdx.x] : 0.f;
#pragma unroll
        for (int o = 16; o; o >>= 1) s += __shfl_xor_sync(0xffffffffu, s, o);
    }
    return s;
}

// ---------------- stage A: i_hat = FFT2(image), s0 ---------------------------
__global__ __launch_bounds__(NT, 1) void kA(const float* __restrict__ img) {
    extern __shared__ float2 sc[];
    __shared__ float s_twr[128], s_twi[128];
    __shared__ float red[32];
    int b = blockIdx.x;
    int tid = threadIdx.x;
    INIT_TWIDDLES();

    float local = 0.f;
    for (int idx = tid; idx < 16384; idx += NT) {
        float v = img[b * 16384 + idx];
        int r = idx >> 7, c = idx & 127;
        sc[r * NPAD + c] = make_float2(v, 0.f);
        local += v;
    }
    float s = block_sum<NT>(local, red);
    if (tid == 0) g_s0[b] = s * (1.f / 16384.f);
    __syncthreads();

    r8_stage<NT, false, 0>(sc, s_twr, s_twi);
    comb_stage<NT, false, 0>(sc, s_twr, s_twi);
    r8_stage<NT, false, 1>(sc, s_twr, s_twi);
    comb_stage<NT, false, 1>(sc, s_twr, s_twi);

    for (int idx = tid; idx < 16384; idx += NT) {
        int r = idx >> 7, c = idx & 127;
        g_ihat[b * 16384 + idx] = sc[r * NPAD + c];
    }
}

// ---------------- stage B: u1 = |ifft2(i_hat*psi)|, s1 partial, u1_hat -------
__global__ __launch_bounds__(NT, 1) void kB() {
    extern __shared__ float2 sc[];
    __shared__ float s_twr[128], s_twi[128];
    __shared__ float red[32];
    int bi = blockIdx.x;              // b*16 + j1*4 + l1
    int b  = bi >> 4;
    int j1 = (bi >> 2) & 3;
    int tid = threadIdx.x;
    INIT_TWIDDLES();
    __syncthreads();

    const float2* src = g_ihat + (size_t)b * 16384;
    const float*  psi1 = g_psi + (((size_t)(bi & 15)) << 14);

    pass_load_inv0<NT>(sc, src, psi1, s_twr, s_twi);
    r8_stage<NT, true, 0>(sc, s_twr, s_twi);
    comb_stage<NT, true, 1>(sc, s_twr, s_twi);
    float local = pass_inv1_r8_mag<NT, true>(sc, s_twr, s_twi);
    float s = block_sum<NT>(local, red);
    if (tid == 0) g_s1part[bi] = s;
    __syncthreads();

    if (j1 < 3) {                     // j1 == 3 never consumed by second order
        r8_stage<NT, false, 0>(sc, s_twr, s_twi);
        comb_stage<NT, false, 0>(sc, s_twr, s_twi);
        r8_stage<NT, false, 1>(sc, s_twr, s_twi);
        pass_fwd1_store<NT>(sc, g_u1hat + (size_t)bi * 16384, s_twr, s_twi);
    }
}

// ---------------- stage C: fp16-smem 4-pass inverse + |.| --------------------
__global__ __launch_bounds__(NTC, 2) void kC() {
    extern __shared__ __half2 sh[];   // 128 rows x SPAD half2 (66 KB)
    __shared__ float s_twr[128], s_twi[128];
    __shared__ float red[32];
    int bi = blockIdx.x;              // b*96 + pair*16 + l1*4 + l2
    int b    = bi / 96;
    int r96  = bi % 96;
    int pair = r96 >> 4;
    int l1   = (r96 >> 2) & 3;
    int l2   = r96 & 3;
    const int J1[6] = {0, 0, 0, 1, 1, 2};
    const int J2[6] = {1, 2, 3, 2, 3, 3};
    int j1 = J1[pair], j2 = J2[pair];
    int tid = threadIdx.x;
    INIT_TWIDDLES();
    __syncthreads();

    const __half2* src = g_u1hat + (((size_t)b * 16 + j1 * 4 + l1) << 14);
    const __half*  psi = g_psih + (((size_t)j2 * 4 + l2) << 14);
    const float scale = 1.f / 16384.f;

    // ---- C1: gmem(half) load * psi -> comb16 inverse (dim0) -> smem --------
#pragma unroll
    for (int it = 0; it < 2; it++) {
        int idx = tid + it * NTC;
        int rr = idx & 127, g = idx >> 7;
        const uint4* s4 = reinterpret_cast<const uint4*>(src + rr * 128 + (g << 4));
        const uint4* p4 = reinterpret_cast<const uint4*>(psi + rr * 128 + (g << 4));
        uint4 sv0 = s4[0], sv1 = s4[1], sv2 = s4[2], sv3 = s4[3];
        uint4 pv0 = p4[0], pv1 = p4[1];
        uint4 svv[4] = {sv0, sv1, sv2, sv3};
        uint4 pvv[2] = {pv0, pv1};
        const __half2* sh2 = reinterpret_cast<const __half2*>(svv);
        const __half*  ph  = reinterpret_cast<const __half*>(pvv);
        float2 x[16];
#pragma unroll
        for (int m = 0; m < 16; m++) {
            float2 v = __half22float2(sh2[m]);
            float  p = __half2float(ph[m]) * scale;
            x[m] = make_float2(v.x * p, v.y * p);
        }
        comb_regs<true>(x, s_twr, s_twi);
        int base = rr * SPAD + (g << 4);
#pragma unroll
        for (int m = 0; m < 16; m++) sh[base + m] = __float22half2_rn(x[m]);
    }
    __syncthreads();

    // ---- C2: inverse r8 along dim0 ------------------------------------------
#pragma unroll
    for (int it = 0; it < 4; it++) {
        int idx = tid + it * NTC;
        int q = idx & 127, j = idx >> 7;          // q = row, j in [0,16)
        int base = q * SPAD + j;
        float2 x[8];
#pragma unroll
        for (int k = 0; k < 8; k++) x[k] = __half22float2(sh[base + 16 * k]);
#pragma unroll
        for (int k = 1; k < 8; k++) {
            int t = j * k;
            float wr = s_twr[t], wi = -s_twi[t];
            float a = x[k].x, bb = x[k].y;
            x[k].x = a * wr - bb * wi; x[k].y = a * wi + bb * wr;
        }
        bfly8<true>(x);
#pragma unroll
        for (int k = 0; k < 8; k++) sh[base + 16 * k] = __float22half2_rn(x[k]);
    }
    __syncthreads();

    // ---- C3: inverse comb16 along dim1 --------------------------------------
#pragma unroll
    for (int it = 0; it < 2; it++) {
        int idx = tid + it * NTC;
        int q = idx & 127, g = idx >> 7;          // q = col, g in [0,8)
        int base = (g << 4) * SPAD + q;
        float2 x[16];
#pragma unroll
        for (int m = 0; m < 16; m++) x[m] = __half22float2(sh[base + m * SPAD]);
        comb_regs<true>(x, s_twr, s_twi);
#pragma unroll
        for (int m = 0; m < 16; m++) sh[base + m * SPAD] = __float22half2_rn(x[m]);
    }
    __syncthreads();

    // ---- C4: inverse r8 along dim1 + |.| (read-only) ------------------------
    float local = 0.f;
#pragma unroll
    for (int it = 0; it < 4; it++) {
        int idx = tid + it * NTC;
        int q = idx & 127, j = idx >> 7;          // q = col, j in [0,16)
        int base = j * SPAD + q;
        int step = 16 * SPAD;
        float2 x[8];
#pragma unroll
        for (int k = 0; k < 8; k++) x[k] = __half22float2(sh[base + k * step]);
#pragma unroll
        for (int k = 1; k < 8; k++) {
            int t = j * k;
            float wr = s_twr[t], wi = -s_twi[t];
            float a = x[k].x, bb = x[k].y;
            x[k].x = a * wr - bb * wi; x[k].y = a * wi + bb * wr;
        }
        bfly8<true>(x);
#pragma unroll
        for (int k = 0; k < 8; k++)
            local += sqrtf(x[k].x * x[k].x + x[k].y * x[k].y);
    }
    float s = block_sum<NTC>(local, red);
    if (tid == 0) g_s2part[bi] = s;
}

// ---------------- stage D: deterministic reduce + MLP ------------------------
__global__ void kD(const float* __restrict__ fc1w, const float* __restrict__ fc1b,
                   const float* __restrict__ fc2w, const float* __restrict__ fc2b,
                   float* __restrict__ out) {
    int b = threadIdx.x;
    if (b >= 64) return;
    float s[11];
    s[0] = g_s0[b];
    for (int j = 0; j < 4; j++) {
        float acc = 0.f;
        for (int l = 0; l < 4; l++) acc += g_s1part[b * 16 + j * 4 + l];
        s[1 + j] = acc * (1.f / (4.f * 16384.f));
    }
    for (int p = 0; p < 6; p++) {
        float acc = 0.f;
        for (int kk = 0; kk < 16; kk++) acc += g_s2part[b * 96 + p * 16 + kk];
        s[5 + p] = acc * (1.f / (16.f * 16384.f));
    }
    float h[4];
    for (int i = 0; i < 4; i++) {
        float a = fc1b[i];
        for (int t = 0; t < 11; t++) a += fc1w[i * 11 + t] * s[t];
        h[i] = fmaxf(a, 0.f);
    }
    for (int kk = 0; kk < 10; kk++) {
        float a = fc2b[kk];
        for (int i = 0; i < 4; i++) a += fc2w[kk * 4 + i] * h[i];
        out[b * 10 + kk] = 1.f / (1.f + expf(-a));
    }
}

// ---------------- launch -----------------------------------------------------
extern "C" void kernel_launch(void* const* d_in, const int* in_sizes, int n_in,
                              void* d_out, int out_size) {
    const float* img  = (const float*)d_in[0];
    const float* fc1w = (const float*)d_in[1];
    const float* fc1b = (const float*)d_in[2];
    const float* fc2w = (const float*)d_in[3];
    const float* fc2b = (const float*)d_in[4];
    float* out = (float*)d_out;

    const size_t smemAB = 128 * NPAD * sizeof(float2);   // 132096 B
    const size_t smemC  = 128 * SPAD * sizeof(__half2);  // 66048 B (2 CTAs/SM)
    cudaFuncSetAttribute(kA, cudaFuncAttributeMaxDynamicSharedMemorySize, (int)smemAB);
    cudaFuncSetAttribute(kB, cudaFuncAttributeMaxDynamicSharedMemorySize, (int)smemAB);
    cudaFuncSetAttribute(kC, cudaFuncAttributeMaxDynamicSharedMemorySize, (int)smemC);

    init_psi_kernel<<<256, 1024>>>();
    kA<<<64, NT, smemAB>>>(img);
    kB<<<1024, NT, smemAB>>>();
    kC<<<6144, NTC, smemC>>>();
    kD<<<1, 64>>>(fc1w, fc1b, fc2w, fc2b, out);
}

// round 12
// speedup vs baseline: 1.5680x; 1.1744x over previous
#include <cuda_runtime.h>
#include <cuda_fp16.h>
#include <math.h>

#define NPAD 129     // fp32 smem layout (kA), float2 units
#define SPAD 129     // fp16 smem layout (kB/kC), half2 units
#define NT   512
#define PI_F 3.14159265358979f

// ---------------- device scratch (static: no allocation allowed) -------------
__device__ float2  g_ihat [64  * 16384];   // FFT2(image), digit-rev layout (fp32)
__device__ __half2 g_u1hat[1024 * 16384];  // FFT2(|u1|),  digit-rev layout (fp16)
__device__ float   g_psi  [16  * 16384];   // Morlet bank, digit-rev (fp32, kB)
__device__ __half  g_psih [16  * 16384];   // Morlet bank, digit-rev (fp16, kC)
__device__ float   g_s0   [64];
__device__ float   g_s1part[1024];
__device__ float   g_s2part[6144];

// digit-reversal for radix [8,4,4] DIF: freq f -> storage position
__device__ __forceinline__ int dperm(int f) {
    return ((f & 7) << 4) | (((f >> 3) & 3) << 2) | (f >> 5);
}

// ---------------- filter bank, stored pre-permuted ---------------------------
__global__ void init_psi_kernel() {
    int idx = blockIdx.x * blockDim.x + threadIdx.x;
    if (idx >= 16 * 16384) return;
    int fc = idx & 127;
    int fr = (idx >> 7) & 127;
    int l  = (idx >> 14) & 3;
    int j  = idx >> 16;
    const float w = 2.f * PI_F / 128.f;
    float fx = (float)((fr < 64) ? fr : fr - 128) * w;
    float fy = (float)((fc < 64) ? fc : fc - 128) * w;
    float k0 = (3.f * PI_F / 4.f) / (float)(1 << j);
    float sg = 0.8f * (float)(1 << j);
    float th = PI_F * (float)l / 4.f;
    float k0x = k0 * cosf(th), k0y = k0 * sinf(th);
    float hs = 0.5f * sg * sg;
    float beta = expf(-hs * k0 * k0);
    float gs = expf(-hs * ((fx - k0x) * (fx - k0x) + (fy - k0y) * (fy - k0y)));
    float g0 = expf(-hs * (fx * fx + fy * fy));
    float v = gs - beta * g0;
    int pos = ((j * 4 + l) << 14) + (dperm(fr) << 7) + dperm(fc);
    g_psi[pos]  = v;
    g_psih[pos] = __float2half(v);
}

// ---------------- register butterflies (interleaved complex) -----------------
template <bool INV>
__device__ __forceinline__ void bfly4(float2* x) {
    float t0r = x[0].x + x[2].x, t0i = x[0].y + x[2].y;
    float t1r = x[0].x - x[2].x, t1i = x[0].y - x[2].y;
    float t2r = x[1].x + x[3].x, t2i = x[1].y + x[3].y;
    float t3r = x[1].x - x[3].x, t3i = x[1].y - x[3].y;
    x[0].x = t0r + t2r; x[0].y = t0i + t2i;
    x[2].x = t0r - t2r; x[2].y = t0i - t2i;
    if (!INV) {
        x[1].x = t1r + t3i; x[1].y = t1i - t3r;
        x[3].x = t1r - t3i; x[3].y = t1i + t3r;
    } else {
        x[1].x = t1r - t3i; x[1].y = t1i + t3r;
        x[3].x = t1r + t3i; x[3].y = t1i - t3r;
    }
}

template <bool INV>
__device__ __forceinline__ void bfly8(float2* x) {
    const float C = 0.70710678118654752f;
    float t0r = x[0].x + x[4].x, t0i = x[0].y + x[4].y;
    float t1r = x[0].x - x[4].x, t1i = x[0].y - x[4].y;
    float t2r = x[2].x + x[6].x, t2i = x[2].y + x[6].y;
    float t3r = x[2].x - x[6].x, t3i = x[2].y - x[6].y;
    float e0r = t0r + t2r, e0i = t0i + t2i;
    float e2r = t0r - t2r, e2i = t0i - t2i;
    float e1r, e1i, e3r, e3i;
    if (!INV) { e1r = t1r + t3i; e1i = t1i - t3r; e3r = t1r - t3i; e3i = t1i + t3r; }
    else      { e1r = t1r - t3i; e1i = t1i + t3r; e3r = t1r + t3i; e3i = t1i - t3r; }
    float u0r = x[1].x + x[5].x, u0i = x[1].y + x[5].y;
    float u1r = x[1].x - x[5].x, u1i = x[1].y - x[5].y;
    float u2r = x[3].x + x[7].x, u2i = x[3].y + x[7].y;
    float u3r = x[3].x - x[7].x, u3i = x[3].y - x[7].y;
    float o0r = u0r + u2r, o0i = u0i + u2i;
    float o2r = u0r - u2r, o2i = u0i - u2i;
    float o1r, o1i, o3r, o3i;
    if (!INV) { o1r = u1r + u3i; o1i = u1i - u3r; o3r = u1r - u3i; o3i = u1i + u3r; }
    else      { o1r = u1r - u3i; o1i = u1i + u3r; o3r = u1r + u3i; o3i = u1i - u3r; }
    float w1r, w1i, w2r, w2i, w3r, w3i;
    if (!INV) {
        w1r = C * (o1r + o1i); w1i = C * (o1i - o1r);
        w2r = o2i;             w2i = -o2r;
        w3r = C * (o3i - o3r); w3i = -C * (o3r + o3i);
    } else {
        w1r = C * (o1r - o1i); w1i = C * (o1i + o1r);
        w2r = -o2i;            w2i = o2r;
        w3r = -C * (o3r + o3i); w3i = C * (o3r - o3i);
    }
    x[0].x = e0r + o0r; x[0].y = e0i + o0i;
    x[1].x = e1r + w1r; x[1].y = e1i + w1i;
    x[2].x = e2r + w2r; x[2].y = e2i + w2i;
    x[3].x = e3r + w3r; x[3].y = e3i + w3i;
    x[4].x = e0r - o0r; x[4].y = e0i - o0i;
    x[5].x = e1r - w1r; x[5].y = e1i - w1i;
    x[6].x = e2r - w2r; x[6].y = e2i - w2i;
    x[7].x = e3r - w3r; x[7].y = e3i - w3i;
}

// ---- combined [r4-mid (stride4) + r4-last (stride1)] on 16 register points --
template <bool INV>
__device__ __forceinline__ void comb_regs(float2* x, const float* twr, const float* twi) {
    if (!INV) {
#pragma unroll
        for (int j = 0; j < 4; j++) {
            float2 y[4];
#pragma unroll
            for (int k = 0; k < 4; k++) y[k] = x[j + 4 * k];
            bfly4<false>(y);
#pragma unroll
            for (int k = 1; k < 4; k++) {
                int ti = 8 * j * k;
                float wr = twr[ti], wi = twi[ti];
                float a = y[k].x, b = y[k].y;
                y[k].x = a * wr - b * wi; y[k].y = a * wi + b * wr;
            }
#pragma unroll
            for (int k = 0; k < 4; k++) x[j + 4 * k] = y[k];
        }
#pragma unroll
        for (int a = 0; a < 4; a++) bfly4<false>(&x[4 * a]);
    } else {
#pragma unroll
        for (int a = 0; a < 4; a++) bfly4<true>(&x[4 * a]);
#pragma unroll
        for (int j = 0; j < 4; j++) {
            float2 y[4];
#pragma unroll
            for (int k = 0; k < 4; k++) y[k] = x[j + 4 * k];
#pragma unroll
            for (int k = 1; k < 4; k++) {
                int ti = 8 * j * k;
                float wr = twr[ti], wi = -twi[ti];
                float a = y[k].x, b = y[k].y;
                y[k].x = a * wr - b * wi; y[k].y = a * wi + b * wr;
            }
            bfly4<true>(y);
#pragma unroll
            for (int k = 0; k < 4; k++) x[j + 4 * k] = y[k];
        }
    }
}

// ---------------- fp32 smem passes (kA only) ---------------------------------
template <int BS, bool INV, int DIM>
__device__ __forceinline__ void comb_stage(float2* sc, const float* twr, const float* twi) {
    for (int idx = threadIdx.x; idx < 1024; idx += BS) {
        int q = idx & 127, g = idx >> 7;
        int base = (DIM == 0) ? q * NPAD + (g << 4) : (g << 4) * NPAD + q;
        int step = (DIM == 0) ? 1 : NPAD;
        float2 x[16];
#pragma unroll
        for (int m = 0; m < 16; m++) x[m] = sc[base + m * step];
        comb_regs<INV>(x, twr, twi);
#pragma unroll
        for (int m = 0; m < 16; m++) sc[base + m * step] = x[m];
    }
    __syncthreads();
}

template <int BS, bool INV, int DIM>
__device__ __forceinline__ void r8_stage(float2* sc, const float* twr, const float* twi) {
    for (int idx = threadIdx.x; idx < 2048; idx += BS) {
        int q = idx & 127, j = idx >> 7;
        int base = (DIM == 0) ? q * NPAD + j : j * NPAD + q;
        int step = (DIM == 0) ? 16 : 16 * NPAD;
        float2 x[8];
#pragma unroll
        for (int k = 0; k < 8; k++) x[k] = sc[base + k * step];
        if (INV) {
#pragma unroll
            for (int k = 1; k < 8; k++) {
                int t = j * k;
                float wr = twr[t], wi = -twi[t];
                float a = x[k].x, b = x[k].y;
                x[k].x = a * wr - b * wi; x[k].y = a * wi + b * wr;
            }
        }
        bfly8<INV>(x);
        if (!INV) {
#pragma unroll
            for (int k = 1; k < 8; k++) {
                int t = j * k;
                float wr = twr[t], wi = twi[t];
                float a = x[k].x, b = x[k].y;
                x[k].x = a * wr - b * wi; x[k].y = a * wi + b * wr;
            }
        }
#pragma unroll
        for (int k = 0; k < 8; k++) sc[base + k * step] = x[k];
    }
    __syncthreads();
}

// ---------------- fp16 smem passes (kB / kC) ---------------------------------
template <int BS, bool INV, int DIM>
__device__ __forceinline__ void hcomb_stage(__half2* sh, const float* twr, const float* twi) {
    for (int idx = threadIdx.x; idx < 1024; idx += BS) {
        int q = idx & 127, g = idx >> 7;
        int base = (DIM == 0) ? q * SPAD + (g << 4) : (g << 4) * SPAD + q;
        int step = (DIM == 0) ? 1 : SPAD;
        float2 x[16];
#pragma unroll
        for (int m = 0; m < 16; m++) x[m] = __half22float2(sh[base + m * step]);
        comb_regs<INV>(x, twr, twi);
#pragma unroll
        for (int m = 0; m < 16; m++) sh[base + m * step] = __float22half2_rn(x[m]);
    }
    __syncthreads();
}

template <int BS, bool INV, int DIM>
__device__ __forceinline__ void hr8_stage(__half2* sh, const float* twr, const float* twi) {
    for (int idx = threadIdx.x; idx < 2048; idx += BS) {
        int q = idx & 127, j = idx >> 7;
        int base = (DIM == 0) ? q * SPAD + j : j * SPAD + q;
        int step = (DIM == 0) ? 16 : 16 * SPAD;
        float2 x[8];
#pragma unroll
        for (int k = 0; k < 8; k++) x[k] = __half22float2(sh[base + k * step]);
        if (INV) {
#pragma unroll
            for (int k = 1; k < 8; k++) {
                int t = j * k;
                float wr = twr[t], wi = -twi[t];
                float a = x[k].x, b = x[k].y;
                x[k].x = a * wr - b * wi; x[k].y = a * wi + b * wr;
            }
        }
        bfly8<INV>(x);
        if (!INV) {
#pragma unroll
            for (int k = 1; k < 8; k++) {
                int t = j * k;
                float wr = twr[t], wi = twi[t];
                float a = x[k].x, b = x[k].y;
                x[k].x = a * wr - b * wi; x[k].y = a * wi + b * wr;
            }
        }
#pragma unroll
        for (int k = 0; k < 8; k++) sh[base + k * step] = __float22half2_rn(x[k]);
    }
    __syncthreads();
}

// kB entry: (fp32 gmem src * fp32 psi * scale) -> comb inv dim0 -> half2 smem
template <int BS>
__device__ __forceinline__ void hpass_load_inv0_f32(__half2* sh, const float2* __restrict__ src,
                                                    const float* __restrict__ psi,
                                                    const float* twr, const float* twi) {
    const float scale = 1.f / 16384.f;
    for (int idx = threadIdx.x; idx < 1024; idx += BS) {
        int rr = idx & 127, g = idx >> 7;
        int gbase = rr * 128 + (g << 4);
        const float4* s4 = reinterpret_cast<const float4*>(src + gbase);
        const float4* p4 = reinterpret_cast<const float4*>(psi + gbase);
        float2 x[16];
#pragma unroll
        for (int m8 = 0; m8 < 4; m8++) {
            float4 p = p4[m8];
            float4 v0 = s4[m8 * 2], v1 = s4[m8 * 2 + 1];
            float pa = p.x * scale, pb = p.y * scale, pc = p.z * scale, pd = p.w * scale;
            x[m8 * 4 + 0] = make_float2(v0.x * pa, v0.y * pa);
            x[m8 * 4 + 1] = make_float2(v0.z * pb, v0.w * pb);
            x[m8 * 4 + 2] = make_float2(v1.x * pc, v1.y * pc);
            x[m8 * 4 + 3] = make_float2(v1.z * pd, v1.w * pd);
        }
        comb_regs<true>(x, twr, twi);
        int base = rr * SPAD + (g << 4);
#pragma unroll
        for (int m = 0; m < 16; m++) sh[base + m] = __float22half2_rn(x[m]);
    }
    __syncthreads();
}

// final inverse r8 dim1 + |.|; optionally write mag back as half2(mag,0)
template <int BS, bool WRITE>
__device__ __forceinline__ float hpass_inv1_r8_mag(__half2* sh, const float* twr, const float* twi) {
    float local = 0.f;
    for (int idx = threadIdx.x; idx < 2048; idx += BS) {
        int q = idx & 127, j = idx >> 7;
        int base = j * SPAD + q;
        int step = 16 * SPAD;
        float2 x[8];
#pragma unroll
        for (int k = 0; k < 8; k++) x[k] = __half22float2(sh[base + k * step]);
#pragma unroll
        for (int k = 1; k < 8; k++) {
            int t = j * k;
            float wr = twr[t], wi = -twi[t];
            float a = x[k].x, b = x[k].y;
            x[k].x = a * wr - b * wi; x[k].y = a * wi + b * wr;
        }
        bfly8<true>(x);
#pragma unroll
        for (int k = 0; k < 8; k++) {
            float mag = sqrtf(x[k].x * x[k].x + x[k].y * x[k].y);
            local += mag;
            if (WRITE) sh[base + k * step] = __floats2half2_rn(mag, 0.f);
        }
    }
    __syncthreads();
    return local;
}

// final forward comb dim1 -> gmem half2 store (coalesced per leg)
template <int BS>
__device__ __forceinline__ void hpass_fwd1_store(__half2* sh, __half2* __restrict__ dst,
                                                 const float* twr, const float* twi) {
    for (int idx = threadIdx.x; idx < 1024; idx += BS) {
        int q = idx & 127, g = idx >> 7;
        int base = (g << 4) * SPAD + q;
        float2 x[16];
#pragma unroll
        for (int m = 0; m < 16; m++) x[m] = __half22float2(sh[base + m * SPAD]);
        comb_regs<false>(x, twr, twi);
#pragma unroll
        for (int m = 0; m < 16; m++)
            dst[((g << 4) + m) * 128 + q] = __float22half2_rn(x[m]);
    }
}

#define INIT_TWIDDLES()                                                        \
    do {                                                                       \
        if (threadIdx.x < 128) {                                               \
            float sv, cv;                                                      \
            __sincosf(-2.f * PI_F * (float)threadIdx.x / 128.f, &sv, &cv);     \
            s_twr[threadIdx.x] = cv;                                           \
            s_twi[threadIdx.x] = sv;                                           \
        }                                                                      \
    } while (0)

// warp-shuffle block reduction (deterministic); result valid in tid 0
template <int BS>
__device__ __forceinline__ float block_sum(float v, float* red) {
#pragma unroll
    for (int o = 16; o; o >>= 1) v += __shfl_xor_sync(0xffffffffu, v, o);
    if ((threadIdx.x & 31) == 0) red[threadIdx.x >> 5] = v;
    __syncthreads();
    float s = 0.f;
    if (threadIdx.x < 32) {
        s = (threadIdx.x < BS / 32) ? red[threadIdx.x] : 0.f;
#pragma unroll
        for (int o = 16; o; o >>= 1) s += __shfl_xor_sync(0xffffffffu, s, o);
    }
    return s;
}

// ---------------- stage A: i_hat = FFT2(image), s0 ---------------------------
__global__ __launch_bounds__(NT, 1) void kA(const float* __restrict__ img) {
    extern __shared__ float2 sc[];
    __shared__ float s_twr[128], s_twi[128];
    __shared__ float red[32];
    int b = blockIdx.x;
    int tid = threadIdx.x;
    INIT_TWIDDLES();

    float local = 0.f;
    for (int idx = tid; idx < 16384; idx += NT) {
        float v = img[b * 16384 + idx];
        int r = idx >> 7, c = idx & 127;
        sc[r * NPAD + c] = make_float2(v, 0.f);
        local += v;
    }
    float s = block_sum<NT>(local, red);
    if (tid == 0) g_s0[b] = s * (1.f / 16384.f);
    __syncthreads();

    r8_stage<NT, false, 0>(sc, s_twr, s_twi);
    comb_stage<NT, false, 0>(sc, s_twr, s_twi);
    r8_stage<NT, false, 1>(sc, s_twr, s_twi);
    comb_stage<NT, false, 1>(sc, s_twr, s_twi);

    for (int idx = tid; idx < 16384; idx += NT) {
        int r = idx >> 7, c = idx & 127;
        g_ihat[b * 16384 + idx] = sc[r * NPAD + c];
    }
}

// ---------------- stage B: u1 = |ifft2(i_hat*psi)|, s1 partial, u1_hat -------
__global__ __launch_bounds__(NT, 2) void kB() {
    extern __shared__ __half2 shb[];
    __shared__ float s_twr[128], s_twi[128];
    __shared__ float red[32];
    int bi = blockIdx.x;              // b*16 + j1*4 + l1
    int b  = bi >> 4;
    int j1 = (bi >> 2) & 3;
    int tid = threadIdx.x;
    INIT_TWIDDLES();
    __syncthreads();

    const float2* src = g_ihat + (size_t)b * 16384;
    const float*  psi1 = g_psi + (((size_t)(bi & 15)) << 14);

    hpass_load_inv0_f32<NT>(shb, src, psi1, s_twr, s_twi);   // inv dim0: comb16
    hr8_stage<NT, true, 0>(shb, s_twr, s_twi);               // inv dim0: r8
    hcomb_stage<NT, true, 1>(shb, s_twr, s_twi);             // inv dim1: comb16
    float local = hpass_inv1_r8_mag<NT, true>(shb, s_twr, s_twi); // inv dim1: r8+mag
    float s = block_sum<NT>(local, red);
    if (tid == 0) g_s1part[bi] = s;
    __syncthreads();

    if (j1 < 3) {                     // j1 == 3 never consumed by second order
        hr8_stage<NT, false, 0>(shb, s_twr, s_twi);
        hcomb_stage<NT, false, 0>(shb, s_twr, s_twi);
        hr8_stage<NT, false, 1>(shb, s_twr, s_twi);
        hpass_fwd1_store<NT>(shb, g_u1hat + (size_t)bi * 16384, s_twr, s_twi);
    }
}

// ---------------- stage C: fp16-smem 4-pass inverse + |.| --------------------
__global__ __launch_bounds__(NT, 2) void kC() {
    extern __shared__ __half2 sh[];
    __shared__ float s_twr[128], s_twi[128];
    __shared__ float red[32];
    int bi = blockIdx.x;              // b*96 + pair*16 + l1*4 + l2
    int b    = bi / 96;
    int r96  = bi % 96;
    int pair = r96 >> 4;
    int l1   = (r96 >> 2) & 3;
    int l2   = r96 & 3;
    const int J1[6] = {0, 0, 0, 1, 1, 2};
    const int J2[6] = {1, 2, 3, 2, 3, 3};
    int j1 = J1[pair], j2 = J2[pair];
    int tid = threadIdx.x;
    INIT_TWIDDLES();
    __syncthreads();

    const __half2* src = g_u1hat + (((size_t)b * 16 + j1 * 4 + l1) << 14);
    const __half*  psi = g_psih + (((size_t)j2 * 4 + l2) << 14);
    const float scale = 1.f / 16384.f;

    // ---- C1: gmem(half) load * psi -> comb16 inverse (dim0) -> smem --------
#pragma unroll
    for (int it = 0; it < 2; it++) {
        int idx = tid + it * NT;
        int rr = idx & 127, g = idx >> 7;
        const uint4* s4 = reinterpret_cast<const uint4*>(src + rr * 128 + (g << 4));
        const uint4* p4 = reinterpret_cast<const uint4*>(psi + rr * 128 + (g << 4));
        uint4 svv[4] = {s4[0], s4[1], s4[2], s4[3]};
        uint4 pvv[2] = {p4[0], p4[1]};
        const __half2* sh2 = reinterpret_cast<const __half2*>(svv);
        const __half*  ph  = reinterpret_cast<const __half*>(pvv);
        float2 x[16];
#pragma unroll
        for (int m = 0; m < 16; m++) {
            float2 v = __half22float2(sh2[m]);
            float  p = __half2float(ph[m]) * scale;
            x[m] = make_float2(v.x * p, v.y * p);
        }
        comb_regs<true>(x, s_twr, s_twi);
        int base = rr * SPAD + (g << 4);
#pragma unroll
        for (int m = 0; m < 16; m++) sh[base + m] = __float22half2_rn(x[m]);
    }
    __syncthreads();

    hr8_stage<NT, true, 0>(sh, s_twr, s_twi);                 // inv dim0: r8
    hcomb_stage<NT, true, 1>(sh, s_twr, s_twi);               // inv dim1: comb16
    float local = hpass_inv1_r8_mag<NT, false>(sh, s_twr, s_twi); // inv dim1: r8+|.|
    float s = block_sum<NT>(local, red);
    if (tid == 0) g_s2part[bi] = s;
}

// ---------------- stage D: deterministic reduce + MLP ------------------------
__global__ void kD(const float* __restrict__ fc1w, const float* __restrict__ fc1b,
                   const float* __restrict__ fc2w, const float* __restrict__ fc2b,
                   float* __restrict__ out) {
    int b = threadIdx.x;
    if (b >= 64) return;
    float s[11];
    s[0] = g_s0[b];
    for (int j = 0; j < 4; j++) {
        float acc = 0.f;
        for (int l = 0; l < 4; l++) acc += g_s1part[b * 16 + j * 4 + l];
        s[1 + j] = acc * (1.f / (4.f * 16384.f));
    }
    for (int p = 0; p < 6; p++) {
        float acc = 0.f;
        for (int kk = 0; kk < 16; kk++) acc += g_s2part[b * 96 + p * 16 + kk];
        s[5 + p] = acc * (1.f / (16.f * 16384.f));
    }
    float h[4];
    for (int i = 0; i < 4; i++) {
        float a = fc1b[i];
        for (int t = 0; t < 11; t++) a += fc1w[i * 11 + t] * s[t];
        h[i] = fmaxf(a, 0.f);
    }
    for (int kk = 0; kk < 10; kk++) {
        float a = fc2b[kk];
        for (int i = 0; i < 4; i++) a += fc2w[kk * 4 + i] * h[i];
        out[b * 10 + kk] = 1.f / (1.f + expf(-a));
    }
}

// ---------------- launch -----------------------------------------------------
extern "C" void kernel_launch(void* const* d_in, const int* in_sizes, int n_in,
                              void* d_out, int out_size) {
    const float* img  = (const float*)d_in[0];
    const float* fc1w = (const float*)d_in[1];
    const float* fc1b = (const float*)d_in[2];
    const float* fc2w = (const float*)d_in[3];
    const float* fc2b = (const float*)d_in[4];
    float* out = (float*)d_out;

    const size_t smemA  = 128 * NPAD * sizeof(float2);   // 132096 B
    const size_t smemBC = 128 * SPAD * sizeof(__half2);  // 66048 B (2 CTAs/SM)
    cudaFuncSetAttribute(kA, cudaFuncAttributeMaxDynamicSharedMemorySize, (int)smemA);
    cudaFuncSetAttribute(kB, cudaFuncAttributeMaxDynamicSharedMemorySize, (int)smemBC);
    cudaFuncSetAttribute(kC, cudaFuncAttributeMaxDynamicSharedMemorySize, (int)smemBC);

    init_psi_kernel<<<256, 1024>>>();
    kA<<<64, NT, smemA>>>(img);
    kB<<<1024, NT, smemBC>>>();
    kC<<<6144, NT, smemBC>>>();
    kD<<<1, 64>>>(fc1w, fc1b, fc2w, fc2b, out);
}